// round 14
// baseline (speedup 1.0000x reference)
#include <cuda_runtime.h>
#include <cuda_fp16.h>
#include <math.h>
#include <stdint.h>

// Problem constants
#define BB 16
#define CC 8
#define LL 16384
#define RR 32

#define TM 256                 // t rows per CTA tile
#define NTILES 8192            // c-major: c=g>>10, b=(g>>6)&15, seg=g&63
#define NBLOCKS 304            // 2 CTAs per SM
#define NTHREADS 256           // 8 warps; warp = m64 x n32 (one n-half)

#define BSTRIDE 132            // uint32 words per B row (264 fp16, padded)

// SMEM layout (bytes): just the fp16 window pair views + queue slot
#define PEH_OFF 0                        // even-pair view: window as halves
#define POH_OFF 1152                     // odd-pair view: window shifted by 1
#define SG_OFF  2304
#define SMEM_BYTES (SG_OFF + 16)         // ~2.3 KB

// Gabor bank, single fp16, padded: row n (0..63) = 2*pos + (0=re,1=im), tap w
__device__ __align__(16) __half g_bh[CC][64 * 2 * BSTRIDE];
__device__ int   g_pr[CC][32];      // sorted pos -> actual output r
// Per-half level tables: [c][h]: .x/.y = kc order nibbles (in-half count desc),
// .z = cum[1..4] bytes (cum[l] = #kc with count >= l)
__device__ uint4 g_tab[CC][2];
__device__ unsigned int g_counter;

__global__ void bank_kernel(const float* __restrict__ kV, const float* __restrict__ sV) {
    int idx = blockIdx.x * blockDim.x + threadIdx.x;
    if (idx >= 65536) return;
    int f = idx >> 8, w = idx & 255;
    int c = f >> 5, j = f & 31;
    float k = kV[f], s = sV[f];

    // sort rank within channel, sigma DESC (pos 0 = largest sigma), tie by j
    int pos = 0;
    for (int j2 = 0; j2 < 32; j2++) {
        float s2 = sV[c * 32 + j2];
        pos += (s2 > s) || (s2 == s && j2 < j);
    }

    float phase = ((float)(-2.0 * M_PI / 256.0) * k) * (float)w;
    double sp, cp;
    sincos((double)phase, &sp, &cp);
    float nm = (float)w - 128.0f;
    float s2v = s * s;
    float inv2s2 = 1.0f / (2.0f * s2v);
    float coef = 1.0f / sqrtf(2.0f * (float)M_PI * s2v);
    float gauss = coef * expf(-inv2s2 * nm * nm);
    float fre = (float)cp * gauss, fim = (float)sp * gauss;

    g_bh[c][(2 * pos) * 264 + w] = __float2half(fre);
    g_bh[c][(2 * pos + 1) * 264 + w] = __float2half(fim);

    if (w == 0) g_pr[c][pos] = 31 - j;   // reference reverses R
}

// Parallel per-channel truncation tables.
__global__ void table_kernel(const float* __restrict__ sV) {
    __shared__ float sg[32];
    __shared__ int kl[8], kh[8];
    int c = blockIdx.x;      // 0..7
    int j = threadIdx.x;     // 0..31
    float s = sV[c * 32 + j];
    int pos = 0;
    for (int j2 = 0; j2 < 32; j2++) {
        float s2 = sV[c * 32 + j2];
        pos += (s2 > s) || (s2 == s && j2 < j);
    }
    sg[pos] = s;             // sigma sorted descending
    __syncthreads();
    if (j < 8) {             // group gq support interval from its max sigma
        float D = 4.5f * sg[4 * j];
        int a = (int)floorf((128.0f - D) * (1.0f / 16.0f));
        int e = (int)floorf((128.0f + D) * (1.0f / 16.0f));
        kl[j] = a < 0 ? 0 : a;
        kh[j] = e > 15 ? 15 : e;
    }
    __syncthreads();
    if (j < 2) {             // per-half counting sort of kc by active count
        int cnt[16];
        for (int kc = 0; kc < 16; kc++) {
            int cn = 0;
            for (int gq = 4 * j; gq < 4 * j + 4; gq++)
                cn += (kl[gq] <= kc && kc <= kh[gq]);
            cnt[kc] = cn;
        }
        unsigned long long ord = 0ull;
        int cum[6];
        int ip = 0;
        for (int l2 = 4; l2 >= 1; l2--) {
            for (int kc = 0; kc < 16; kc++)
                if (cnt[kc] == l2) {
                    ord |= (unsigned long long)kc << (4 * ip);
                    ip++;
                }
            cum[l2] = ip;
        }
        uint4 tab;
        tab.x = (unsigned int)(ord & 0xFFFFFFFFull);
        tab.y = (unsigned int)(ord >> 32);
        tab.z = (unsigned int)cum[1] | ((unsigned int)cum[2] << 8) |
                ((unsigned int)cum[3] << 16) | ((unsigned int)cum[4] << 24);
        tab.w = 0;
        g_tab[c][j] = tab;
    }
    if (c == 0 && j == 0) g_counter = 0;
}

__device__ __forceinline__ void mma16816(float* d,
                                         uint32_t a0, uint32_t a1, uint32_t a2, uint32_t a3,
                                         uint32_t b0, uint32_t b1) {
    asm volatile(
        "mma.sync.aligned.m16n8k16.row.col.f32.f16.f16.f32 "
        "{%0,%1,%2,%3}, {%4,%5,%6,%7}, {%8,%9}, {%0,%1,%2,%3};"
        : "+f"(d[0]), "+f"(d[1]), "+f"(d[2]), "+f"(d[3])
        : "r"(a0), "r"(a1), "r"(a2), "r"(a3), "r"(b0), "r"(b1));
}

__global__ void __launch_bounds__(NTHREADS, 2)
conv_kernel(const float* __restrict__ x, float* __restrict__ out) {
    extern __shared__ unsigned char smem[];
    __half* PEh = (__half*)(smem + PEH_OFF);   // PEh[j] = half(window[j])
    __half* POh = (__half*)(smem + POH_OFF);   // POh[j] = half(window[j+1])
    const uint32_t* SW = (const uint32_t*)smem;
    unsigned int* sgp = (unsigned int*)(smem + SG_OFF);

    int tid  = threadIdx.x;
    int wid  = tid >> 5;
    int lane = tid & 31;
    int lq   = lane >> 2;     // 0..7
    int lr   = lane & 3;      // 0..3
    int half = wid & 1;       // n-half: groups 4*half .. 4*half+3
    int mwarp = (wid >> 1) * 64;
    int odd = lq & 1;
    int abase = (mwarp >> 1) + (lq >> 1) + lr;

    // A pair-array word offset (PE/PO selected by odd)
    int awH = (odd ? POH_OFF : PEH_OFF) / 4 + abase;
    // B word offset within the channel's bank image (global, L1/L2-resident)
    int blW = (4 * half) * 8 * BSTRIDE + lq * BSTRIDE + lr;

    if (tid == 0) sgp[0] = atomicAdd(&g_counter, 1u);
    __syncthreads();
    unsigned int g = sgp[0];

    // prefetch first tile's x window: window[j] = x[b, t0-128+j, c], j<544
    float v0 = 0, v1 = 0;
    {
        unsigned int gc = (g < NTILES) ? g : 0u;
        int c2 = gc >> 10, b2 = (gc >> 6) & 15, t02 = (int)(gc & 63) << 8;
        const float* xb = x + (size_t)b2 * LL * CC + c2;
        int l = t02 - 128 + tid;
        v0 = (l >= 0 && l < LL) ? xb[(size_t)l * CC] : 0.0f;
        if (tid < 288) {
            int l1 = l + 256;
            v1 = (l1 >= 0 && l1 < LL) ? xb[(size_t)l1 * CC] : 0.0f;
        }
    }

    int cur_c = -1;
    const uint32_t* gB = (const uint32_t*)g_bh[0];
    unsigned long long ordv = 0ull;
    int cum1 = 0, cum2 = 0, cum3 = 0, cum4 = 0;
    int rcol[4];
    while (g < NTILES) {
        int c = g >> 10, b = (g >> 6) & 15, t0 = (int)(g & 63) << 8;

        __syncthreads();   // B1: previous tile's smem readers done

        if (c != cur_c) {  // per-channel tables only (B read direct from L2)
            gB = (const uint32_t*)g_bh[c];
            uint4 tab = g_tab[c][half];
            ordv = (unsigned long long)tab.x | ((unsigned long long)tab.y << 32);
            cum1 = (int)(tab.z & 255u);
            cum2 = (int)((tab.z >> 8) & 255u);
            cum3 = (int)((tab.z >> 16) & 255u);
            cum4 = (int)((tab.z >> 24) & 255u);
#pragma unroll
            for (int gq = 0; gq < 4; gq++)
                rcol[gq] = c * RR + g_pr[c][(4 * half + gq) * 4 + lr];
            cur_c = c;
        }

        // store fp16 window directly (PE = window, PO = window shifted by 1)
        {
            __half h0 = __float2half(v0);
            PEh[tid] = h0;
            if (tid > 0) POh[tid - 1] = h0;
            if (tid < 288) {
                __half h1 = __float2half(v1);
                PEh[256 + tid] = h1;
                POh[255 + tid] = h1;
            }
        }
        if (tid == 0) sgp[1] = atomicAdd(&g_counter, 1u);
        __syncthreads();   // B2: window + next-tile id visible
        unsigned int gn = sgp[1];

        // prefetch next tile's x (hidden under the MMA mainloop)
        {
            unsigned int gc = (gn < NTILES) ? gn : 0u;
            int c2 = gc >> 10, b2 = (gc >> 6) & 15, t02 = (int)(gc & 63) << 8;
            const float* xb = x + (size_t)b2 * LL * CC + c2;
            int l = t02 - 128 + tid;
            v0 = (l >= 0 && l < LL) ? xb[(size_t)l * CC] : 0.0f;
            if (tid < 288) {
                int l1 = l + 256;
                v1 = (l1 >= 0 && l1 < LL) ? xb[(size_t)l1 * CC] : 0.0f;
            }
        }

        // ---- single-pass fp16 GEMM, per-half level-loop truncation ----
        // A from smem pair views; B fragments uniform-loaded straight from
        // the global bank (L1/L2 resident; ~46 words per warp per tile).
        float d[64];
#pragma unroll
        for (int i = 0; i < 64; i++) d[i] = 0.0f;

#pragma unroll
        for (int lv = 4; lv >= 1; lv--) {
            int i0 = (lv == 4) ? 0 : ((lv == 3) ? cum4 : ((lv == 2) ? cum3 : cum2));
            int i1 = (lv == 4) ? cum4 : ((lv == 3) ? cum3 : ((lv == 2) ? cum2 : cum1));
#pragma unroll 1
            for (int idx = i0; idx < i1; idx++) {
                int kc = (int)((ordv >> (4 * idx)) & 15ull);
                int ah = awH + kc * 8;
                const uint32_t* bk = gB + blW + kc * 8;
                uint32_t w9[9];
#pragma unroll
                for (int u = 0; u < 9; u++) w9[u] = SW[ah + 4 * u];
#pragma unroll
                for (int gq = 0; gq < lv; gq++) {
                    uint32_t b0 = __ldg(bk + gq * 8 * BSTRIDE);
                    uint32_t b1 = __ldg(bk + gq * 8 * BSTRIDE + 4);
#pragma unroll
                    for (int ms = 0; ms < 4; ms++)
                        mma16816(d + (ms * 4 + gq) * 4,
                                 w9[2 * ms], w9[2 * ms + 1],
                                 w9[2 * ms + 1], w9[2 * ms + 2], b0, b1);
                }
            }
        }

        // ---- epilogue: power + permuted store ----
        size_t ob = ((size_t)(b * LL + t0 + mwarp + lq)) * (CC * RR);
#pragma unroll
        for (int ms = 0; ms < 4; ms++) {
#pragma unroll
            for (int gq = 0; gq < 4; gq++) {
                const float* dd = d + (ms * 4 + gq) * 4;
                float p0 = dd[0] * dd[0] + dd[1] * dd[1];
                float p1 = dd[2] * dd[2] + dd[3] * dd[3];
                out[ob + (size_t)(ms * 16) * (CC * RR) + rcol[gq]] = p0;
                out[ob + (size_t)(ms * 16 + 8) * (CC * RR) + rcol[gq]] = p1;
            }
        }

        g = gn;
    }
}

extern "C" void kernel_launch(void* const* d_in, const int* in_sizes, int n_in,
                              void* d_out, int out_size) {
    const float* x  = (const float*)d_in[0];
    const float* kV = (const float*)d_in[1];
    const float* sV = (const float*)d_in[2];
    float* out = (float*)d_out;

    cudaFuncSetAttribute(conv_kernel, cudaFuncAttributeMaxDynamicSharedMemorySize,
                         SMEM_BYTES);

    // 1) Gabor bank (sigma-sorted, single fp16)
    bank_kernel<<<256, 256>>>(kV, sV);
    // 2) per-channel truncation tables + queue reset (parallel)
    table_kernel<<<CC, 32>>>(sV);
    // 3) persistent implicit-GEMM wavelet transform (B direct from L2)
    conv_kernel<<<NBLOCKS, NTHREADS, SMEM_BYTES>>>(x, out);
}

// round 15
// speedup vs baseline: 1.1797x; 1.1797x over previous
#include <cuda_runtime.h>
#include <cuda_fp16.h>
#include <math.h>
#include <stdint.h>

// Problem constants
#define BB 16
#define CC 8
#define LL 16384
#define RR 32

#define TM 256                 // t rows per CTA tile
#define NTILES 8192            // c-major: c=g>>10, b=(g>>6)&15, seg=g&63
#define NBLOCKS 304            // 2 CTAs per SM
#define NTHREADS 256           // 8 warps; warp = m64 x n32 (one n-half)

#define BSTRIDE 132            // uint32 words per B row (264 fp16, padded)

// SMEM layout (bytes)
#define BH_OFF 0                         // B: 64 rows * 132 words = 33792 B
#define PB_OFF 33792                     // window pair views, 2 buffers:
                                         //   buf*2304 + {PE:0, PO:1152}
#define SG_OFF (PB_OFF + 4608)           // queue slots [0],[1] + initial [2]
#define SMEM_BYTES (SG_OFF + 16)         // ~38.4 KB -> 2 CTAs/SM

// Gabor bank, single fp16, padded: row n (0..63) = 2*pos + (0=re,1=im), tap w
__device__ __align__(16) __half g_bh[CC][64 * 2 * BSTRIDE];
__device__ int   g_pr[CC][32];      // sorted pos -> actual output r
// Per-half level tables: [c][h]: .x/.y = kc order nibbles (in-half count desc),
// .z = cum[1..4] bytes (cum[l] = #kc with count >= l)
__device__ uint4 g_tab[CC][2];
__device__ unsigned int g_counter;

__global__ void bank_kernel(const float* __restrict__ kV, const float* __restrict__ sV) {
    int idx = blockIdx.x * blockDim.x + threadIdx.x;
    if (idx >= 65536) return;
    int f = idx >> 8, w = idx & 255;
    int c = f >> 5, j = f & 31;
    float k = kV[f], s = sV[f];

    // sort rank within channel, sigma DESC (pos 0 = largest sigma), tie by j
    int pos = 0;
    for (int j2 = 0; j2 < 32; j2++) {
        float s2 = sV[c * 32 + j2];
        pos += (s2 > s) || (s2 == s && j2 < j);
    }

    float phase = ((float)(-2.0 * M_PI / 256.0) * k) * (float)w;
    double sp, cp;
    sincos((double)phase, &sp, &cp);
    float nm = (float)w - 128.0f;
    float s2v = s * s;
    float inv2s2 = 1.0f / (2.0f * s2v);
    float coef = 1.0f / sqrtf(2.0f * (float)M_PI * s2v);
    float gauss = coef * expf(-inv2s2 * nm * nm);
    float fre = (float)cp * gauss, fim = (float)sp * gauss;

    g_bh[c][(2 * pos) * 264 + w] = __float2half(fre);
    g_bh[c][(2 * pos + 1) * 264 + w] = __float2half(fim);

    if (w == 0) g_pr[c][pos] = 31 - j;   // reference reverses R
}

// Parallel per-channel truncation tables.
__global__ void table_kernel(const float* __restrict__ sV) {
    __shared__ float sg[32];
    __shared__ int kl[8], kh[8];
    int c = blockIdx.x;      // 0..7
    int j = threadIdx.x;     // 0..31
    float s = sV[c * 32 + j];
    int pos = 0;
    for (int j2 = 0; j2 < 32; j2++) {
        float s2 = sV[c * 32 + j2];
        pos += (s2 > s) || (s2 == s && j2 < j);
    }
    sg[pos] = s;             // sigma sorted descending
    __syncthreads();
    if (j < 8) {             // group gq support interval from its max sigma
        float D = 4.5f * sg[4 * j];
        int a = (int)floorf((128.0f - D) * (1.0f / 16.0f));
        int e = (int)floorf((128.0f + D) * (1.0f / 16.0f));
        kl[j] = a < 0 ? 0 : a;
        kh[j] = e > 15 ? 15 : e;
    }
    __syncthreads();
    if (j < 2) {             // per-half counting sort of kc by active count
        int cnt[16];
        for (int kc = 0; kc < 16; kc++) {
            int cn = 0;
            for (int gq = 4 * j; gq < 4 * j + 4; gq++)
                cn += (kl[gq] <= kc && kc <= kh[gq]);
            cnt[kc] = cn;
        }
        unsigned long long ord = 0ull;
        int cum[6];
        int ip = 0;
        for (int l2 = 4; l2 >= 1; l2--) {
            for (int kc = 0; kc < 16; kc++)
                if (cnt[kc] == l2) {
                    ord |= (unsigned long long)kc << (4 * ip);
                    ip++;
                }
            cum[l2] = ip;
        }
        uint4 tab;
        tab.x = (unsigned int)(ord & 0xFFFFFFFFull);
        tab.y = (unsigned int)(ord >> 32);
        tab.z = (unsigned int)cum[1] | ((unsigned int)cum[2] << 8) |
                ((unsigned int)cum[3] << 16) | ((unsigned int)cum[4] << 24);
        tab.w = 0;
        g_tab[c][j] = tab;
    }
    if (c == 0 && j == 0) g_counter = 0;
}

__device__ __forceinline__ void mma16816(float* d,
                                         uint32_t a0, uint32_t a1, uint32_t a2, uint32_t a3,
                                         uint32_t b0, uint32_t b1) {
    asm volatile(
        "mma.sync.aligned.m16n8k16.row.col.f32.f16.f16.f32 "
        "{%0,%1,%2,%3}, {%4,%5,%6,%7}, {%8,%9}, {%0,%1,%2,%3};"
        : "+f"(d[0]), "+f"(d[1]), "+f"(d[2]), "+f"(d[3])
        : "r"(a0), "r"(a1), "r"(a2), "r"(a3), "r"(b0), "r"(b1));
}

__global__ void __launch_bounds__(NTHREADS, 2)
conv_kernel(const float* __restrict__ x, float* __restrict__ out) {
    extern __shared__ unsigned char smem[];
    const uint32_t* SW = (const uint32_t*)smem;     // word-indexed smem base
    unsigned int* sgp = (unsigned int*)(smem + SG_OFF);

    int tid  = threadIdx.x;
    int wid  = tid >> 5;
    int lane = tid & 31;
    int lq   = lane >> 2;     // 0..7
    int lr   = lane & 3;      // 0..3
    int half = wid & 1;       // n-half: groups 4*half .. 4*half+3
    int mwarp = (wid >> 1) * 64;
    int odd = lq & 1;
    int abase = (mwarp >> 1) + (lq >> 1) + lr;

    // word offsets: A pair view base (without buffer), B rows in staged SMEM
    int awH0 = (PB_OFF + (odd ? 1152 : 0)) / 4 + abase;
    int blW  = BH_OFF / 4 + (4 * half) * 8 * BSTRIDE + lq * BSTRIDE + lr;

    if (tid == 0) sgp[2] = atomicAdd(&g_counter, 1u);
    __syncthreads();
    unsigned int g = sgp[2];

    // prefetch first tile's x window: window[j] = x[b, t0-128+j, c], j<544
    float v0 = 0, v1 = 0;
    {
        unsigned int gc = (g < NTILES) ? g : 0u;
        int c2 = gc >> 10, b2 = (gc >> 6) & 15, t02 = (int)(gc & 63) << 8;
        const float* xb = x + (size_t)b2 * LL * CC + c2;
        int l = t02 - 128 + tid;
        v0 = (l >= 0 && l < LL) ? xb[(size_t)l * CC] : 0.0f;
        if (tid < 288) {
            int l1 = l + 256;
            v1 = (l1 >= 0 && l1 < LL) ? xb[(size_t)l1 * CC] : 0.0f;
        }
    }

    int cur_c = -1;
    unsigned long long ordv = 0ull;
    int cum1 = 0, cum2 = 0, cum3 = 0, cum4 = 0;
    int rcol[4];
    int buf = 0;
    while (g < NTILES) {
        int c = g >> 10, b = (g >> 6) & 15, t0 = (int)(g & 63) << 8;

        // store fp16 window into THIS buffer (alternate => no read-protect
        // barrier needed; all warps passed last tile's barrier after their
        // reads of this buffer two tiles ago)
        {
            __half* PEh = (__half*)(smem + PB_OFF + buf * 2304);
            __half* POh = PEh + 576;     // 1152 B later
            __half h0 = __float2half(v0);
            PEh[tid] = h0;
            if (tid > 0) POh[tid - 1] = h0;
            if (tid < 288) {
                __half h1 = __float2half(v1);
                PEh[256 + tid] = h1;
                POh[255 + tid] = h1;
            }
        }

        if (c != cur_c) {  // stage B for this channel (rare; own barrier)
            __syncthreads();           // protect previous tile's B readers
            const uint4* sH = (const uint4*)g_bh[c];
            uint4* dH = (uint4*)(smem + BH_OFF);
            for (int i = tid; i < 2112; i += NTHREADS) dH[i] = sH[i];
            uint4 tab = g_tab[c][half];
            ordv = (unsigned long long)tab.x | ((unsigned long long)tab.y << 32);
            cum1 = (int)(tab.z & 255u);
            cum2 = (int)((tab.z >> 8) & 255u);
            cum3 = (int)((tab.z >> 16) & 255u);
            cum4 = (int)((tab.z >> 24) & 255u);
#pragma unroll
            for (int gq = 0; gq < 4; gq++)
                rcol[gq] = c * RR + g_pr[c][(4 * half + gq) * 4 + lr];
            cur_c = c;
        }

        if (tid == 0) sgp[buf] = atomicAdd(&g_counter, 1u);
        __syncthreads();   // THE one per-tile barrier: window+B+id visible
        unsigned int gn = sgp[buf];

        // prefetch next tile's x (hidden under the MMA mainloop)
        {
            unsigned int gc = (gn < NTILES) ? gn : 0u;
            int c2 = gc >> 10, b2 = (gc >> 6) & 15, t02 = (int)(gc & 63) << 8;
            const float* xb = x + (size_t)b2 * LL * CC + c2;
            int l = t02 - 128 + tid;
            v0 = (l >= 0 && l < LL) ? xb[(size_t)l * CC] : 0.0f;
            if (tid < 288) {
                int l1 = l + 256;
                v1 = (l1 >= 0 && l1 < LL) ? xb[(size_t)l1 * CC] : 0.0f;
            }
        }

        // ---- single-pass fp16 GEMM, per-half level-loop truncation ----
        // Per kc: batch-load 9 A words + all 2*lv B words (independent LDS,
        // latency overlapped), then a pure MMA burst. Compile-time acc idx.
        float d[64];
#pragma unroll
        for (int i = 0; i < 64; i++) d[i] = 0.0f;

        int awB = awH0 + buf * 576;
#pragma unroll
        for (int lv = 4; lv >= 1; lv--) {
            int i0 = (lv == 4) ? 0 : ((lv == 3) ? cum4 : ((lv == 2) ? cum3 : cum2));
            int i1 = (lv == 4) ? cum4 : ((lv == 3) ? cum3 : ((lv == 2) ? cum2 : cum1));
#pragma unroll 1
            for (int idx = i0; idx < i1; idx++) {
                int kc = (int)((ordv >> (4 * idx)) & 15ull);
                int ah = awB + kc * 8;
                int bh = blW + kc * 8;
                uint32_t w9[9];
#pragma unroll
                for (int u = 0; u < 9; u++) w9[u] = SW[ah + 4 * u];
                uint32_t bb[8];
#pragma unroll
                for (int gq = 0; gq < lv; gq++) {
                    bb[2 * gq]     = SW[bh + gq * 8 * BSTRIDE];
                    bb[2 * gq + 1] = SW[bh + gq * 8 * BSTRIDE + 4];
                }
#pragma unroll
                for (int gq = 0; gq < lv; gq++)
#pragma unroll
                    for (int ms = 0; ms < 4; ms++)
                        mma16816(d + (ms * 4 + gq) * 4,
                                 w9[2 * ms], w9[2 * ms + 1],
                                 w9[2 * ms + 1], w9[2 * ms + 2],
                                 bb[2 * gq], bb[2 * gq + 1]);
            }
        }

        // ---- epilogue: power + permuted store ----
        size_t ob = ((size_t)(b * LL + t0 + mwarp + lq)) * (CC * RR);
#pragma unroll
        for (int ms = 0; ms < 4; ms++) {
#pragma unroll
            for (int gq = 0; gq < 4; gq++) {
                const float* dd = d + (ms * 4 + gq) * 4;
                float p0 = dd[0] * dd[0] + dd[1] * dd[1];
                float p1 = dd[2] * dd[2] + dd[3] * dd[3];
                out[ob + (size_t)(ms * 16) * (CC * RR) + rcol[gq]] = p0;
                out[ob + (size_t)(ms * 16 + 8) * (CC * RR) + rcol[gq]] = p1;
            }
        }

        g = gn;
        buf ^= 1;
    }
}

extern "C" void kernel_launch(void* const* d_in, const int* in_sizes, int n_in,
                              void* d_out, int out_size) {
    const float* x  = (const float*)d_in[0];
    const float* kV = (const float*)d_in[1];
    const float* sV = (const float*)d_in[2];
    float* out = (float*)d_out;

    cudaFuncSetAttribute(conv_kernel, cudaFuncAttributeMaxDynamicSharedMemorySize,
                         SMEM_BYTES);

    // 1) Gabor bank (sigma-sorted, single fp16)
    bank_kernel<<<256, 256>>>(kV, sV);
    // 2) per-channel truncation tables + queue reset (parallel)
    table_kernel<<<CC, 32>>>(sV);
    // 3) persistent implicit-GEMM wavelet transform (B in SMEM, 1 barrier/tile)
    conv_kernel<<<NBLOCKS, NTHREADS, SMEM_BYTES>>>(x, out);
}

// round 16
// speedup vs baseline: 1.4633x; 1.2404x over previous
#include <cuda_runtime.h>
#include <cuda_fp16.h>
#include <math.h>
#include <stdint.h>

// Problem constants
#define BB 16
#define CC 8
#define LL 16384
#define RR 32

#define TM 256                 // t rows per CTA tile
#define NTILES 8192            // c-major: c=g>>10, b=(g>>6)&15, seg=g&63
#define NBLOCKS 304            // 2 CTAs per SM
#define NTHREADS 256           // 8 warps; warp = m64 x n32 (one n-half)

#define BSTRIDE 132            // uint32 words per B row (264 fp16, padded)

// SMEM layout (bytes)
#define BH_OFF 0                         // B: 64 rows * 132 words = 33792 B
#define PB_OFF 33792                     // window pair views, 2 buffers:
                                         //   buf*2304 + {PE:0, PO:1152}
#define SG_OFF (PB_OFF + 4608)           // queue slots [0],[1] + initial [2]
#define OUT_OFF (SG_OFF + 16)            // output stage: 256 rows * 36 floats
#define SMEM_BYTES (OUT_OFF + 256 * 36 * 4)   // ~75.3 KB -> 2 CTAs/SM

// Gabor bank, single fp16, padded: row n (0..63) = 2*pos + (0=re,1=im), tap w
__device__ __align__(16) __half g_bh[CC][64 * 2 * BSTRIDE];
__device__ int   g_pr[CC][32];      // sorted pos -> actual output r
// Per-half level tables: [c][h]: .x/.y = kc order nibbles (in-half count desc),
// .z = cum[1..4] bytes (cum[l] = #kc with count >= l)
__device__ uint4 g_tab[CC][2];
__device__ unsigned int g_counter;

__global__ void bank_kernel(const float* __restrict__ kV, const float* __restrict__ sV) {
    int idx = blockIdx.x * blockDim.x + threadIdx.x;
    if (idx >= 65536) return;
    int f = idx >> 8, w = idx & 255;
    int c = f >> 5, j = f & 31;
    float k = kV[f], s = sV[f];

    // sort rank within channel, sigma DESC (pos 0 = largest sigma), tie by j
    int pos = 0;
    for (int j2 = 0; j2 < 32; j2++) {
        float s2 = sV[c * 32 + j2];
        pos += (s2 > s) || (s2 == s && j2 < j);
    }

    float phase = ((float)(-2.0 * M_PI / 256.0) * k) * (float)w;
    double sp, cp;
    sincos((double)phase, &sp, &cp);
    float nm = (float)w - 128.0f;
    float s2v = s * s;
    float inv2s2 = 1.0f / (2.0f * s2v);
    float coef = 1.0f / sqrtf(2.0f * (float)M_PI * s2v);
    float gauss = coef * expf(-inv2s2 * nm * nm);
    float fre = (float)cp * gauss, fim = (float)sp * gauss;

    g_bh[c][(2 * pos) * 264 + w] = __float2half(fre);
    g_bh[c][(2 * pos + 1) * 264 + w] = __float2half(fim);

    if (w == 0) g_pr[c][pos] = 31 - j;   // reference reverses R
}

// Parallel per-channel truncation tables.
__global__ void table_kernel(const float* __restrict__ sV) {
    __shared__ float sg[32];
    __shared__ int kl[8], kh[8];
    int c = blockIdx.x;      // 0..7
    int j = threadIdx.x;     // 0..31
    float s = sV[c * 32 + j];
    int pos = 0;
    for (int j2 = 0; j2 < 32; j2++) {
        float s2 = sV[c * 32 + j2];
        pos += (s2 > s) || (s2 == s && j2 < j);
    }
    sg[pos] = s;             // sigma sorted descending
    __syncthreads();
    if (j < 8) {             // group gq support interval from its max sigma
        float D = 4.5f * sg[4 * j];
        int a = (int)floorf((128.0f - D) * (1.0f / 16.0f));
        int e = (int)floorf((128.0f + D) * (1.0f / 16.0f));
        kl[j] = a < 0 ? 0 : a;
        kh[j] = e > 15 ? 15 : e;
    }
    __syncthreads();
    if (j < 2) {             // per-half counting sort of kc by active count
        int cnt[16];
        for (int kc = 0; kc < 16; kc++) {
            int cn = 0;
            for (int gq = 4 * j; gq < 4 * j + 4; gq++)
                cn += (kl[gq] <= kc && kc <= kh[gq]);
            cnt[kc] = cn;
        }
        unsigned long long ord = 0ull;
        int cum[6];
        int ip = 0;
        for (int l2 = 4; l2 >= 1; l2--) {
            for (int kc = 0; kc < 16; kc++)
                if (cnt[kc] == l2) {
                    ord |= (unsigned long long)kc << (4 * ip);
                    ip++;
                }
            cum[l2] = ip;
        }
        uint4 tab;
        tab.x = (unsigned int)(ord & 0xFFFFFFFFull);
        tab.y = (unsigned int)(ord >> 32);
        tab.z = (unsigned int)cum[1] | ((unsigned int)cum[2] << 8) |
                ((unsigned int)cum[3] << 16) | ((unsigned int)cum[4] << 24);
        tab.w = 0;
        g_tab[c][j] = tab;
    }
    if (c == 0 && j == 0) g_counter = 0;
}

__device__ __forceinline__ void mma16816(float* d,
                                         uint32_t a0, uint32_t a1, uint32_t a2, uint32_t a3,
                                         uint32_t b0, uint32_t b1) {
    asm volatile(
        "mma.sync.aligned.m16n8k16.row.col.f32.f16.f16.f32 "
        "{%0,%1,%2,%3}, {%4,%5,%6,%7}, {%8,%9}, {%0,%1,%2,%3};"
        : "+f"(d[0]), "+f"(d[1]), "+f"(d[2]), "+f"(d[3])
        : "r"(a0), "r"(a1), "r"(a2), "r"(a3), "r"(b0), "r"(b1));
}

__global__ void __launch_bounds__(NTHREADS, 2)
conv_kernel(const float* __restrict__ x, float* __restrict__ out) {
    extern __shared__ unsigned char smem[];
    const uint32_t* SW = (const uint32_t*)smem;     // word-indexed smem base
    unsigned int* sgp = (unsigned int*)(smem + SG_OFF);
    float* so = (float*)(smem + OUT_OFF);           // output stage [256][36]

    int tid  = threadIdx.x;
    int wid  = tid >> 5;
    int lane = tid & 31;
    int lq   = lane >> 2;     // 0..7
    int lr   = lane & 3;      // 0..3
    int half = wid & 1;       // n-half: groups 4*half .. 4*half+3
    int mwarp = (wid >> 1) * 64;
    int odd = lq & 1;
    int abase = (mwarp >> 1) + (lq >> 1) + lr;

    // word offsets: A pair view base (without buffer), B rows in staged SMEM
    int awH0 = (PB_OFF + (odd ? 1152 : 0)) / 4 + abase;
    int blW  = BH_OFF / 4 + (4 * half) * 8 * BSTRIDE + lq * BSTRIDE + lr;

    if (tid == 0) sgp[2] = atomicAdd(&g_counter, 1u);
    __syncthreads();
    unsigned int g = sgp[2];

    // prefetch first tile's x window: window[j] = x[b, t0-128+j, c], j<544
    float v0 = 0, v1 = 0;
    {
        unsigned int gc = (g < NTILES) ? g : 0u;
        int c2 = gc >> 10, b2 = (gc >> 6) & 15, t02 = (int)(gc & 63) << 8;
        const float* xb = x + (size_t)b2 * LL * CC + c2;
        int l = t02 - 128 + tid;
        v0 = (l >= 0 && l < LL) ? xb[(size_t)l * CC] : 0.0f;
        if (tid < 288) {
            int l1 = l + 256;
            v1 = (l1 >= 0 && l1 < LL) ? xb[(size_t)l1 * CC] : 0.0f;
        }
    }

    int cur_c = -1;
    unsigned long long ordv = 0ull;
    int cum1 = 0, cum2 = 0, cum3 = 0, cum4 = 0;
    int lcol[4];
    int buf = 0;
    while (g < NTILES) {
        int c = g >> 10, b = (g >> 6) & 15, t0 = (int)(g & 63) << 8;

        // store fp16 window into THIS buffer (alternate buffers; previous
        // readers of it are fenced by an earlier barrier)
        {
            __half* PEh = (__half*)(smem + PB_OFF + buf * 2304);
            __half* POh = PEh + 576;     // 1152 B later
            __half h0 = __float2half(v0);
            PEh[tid] = h0;
            if (tid > 0) POh[tid - 1] = h0;
            if (tid < 288) {
                __half h1 = __float2half(v1);
                PEh[256 + tid] = h1;
                POh[255 + tid] = h1;
            }
        }

        if (c != cur_c) {  // stage B for this channel (rare; own barrier)
            __syncthreads();           // protect previous tile's B readers
            const uint4* sH = (const uint4*)g_bh[c];
            uint4* dH = (uint4*)(smem + BH_OFF);
            for (int i = tid; i < 2112; i += NTHREADS) dH[i] = sH[i];
            uint4 tab = g_tab[c][half];
            ordv = (unsigned long long)tab.x | ((unsigned long long)tab.y << 32);
            cum1 = (int)(tab.z & 255u);
            cum2 = (int)((tab.z >> 8) & 255u);
            cum3 = (int)((tab.z >> 16) & 255u);
            cum4 = (int)((tab.z >> 24) & 255u);
#pragma unroll
            for (int gq = 0; gq < 4; gq++)
                lcol[gq] = g_pr[c][(4 * half + gq) * 4 + lr];
            cur_c = c;
        }

        if (tid == 0) sgp[buf] = atomicAdd(&g_counter, 1u);
        __syncthreads();   // barrier A: window+B+id visible; prev out reads done
        unsigned int gn = sgp[buf];

        // prefetch next tile's x (hidden under the MMA mainloop)
        {
            unsigned int gc = (gn < NTILES) ? gn : 0u;
            int c2 = gc >> 10, b2 = (gc >> 6) & 15, t02 = (int)(gc & 63) << 8;
            const float* xb = x + (size_t)b2 * LL * CC + c2;
            int l = t02 - 128 + tid;
            v0 = (l >= 0 && l < LL) ? xb[(size_t)l * CC] : 0.0f;
            if (tid < 288) {
                int l1 = l + 256;
                v1 = (l1 >= 0 && l1 < LL) ? xb[(size_t)l1 * CC] : 0.0f;
            }
        }

        // ---- single-pass fp16 GEMM, per-half level-loop truncation ----
        float d[64];
#pragma unroll
        for (int i = 0; i < 64; i++) d[i] = 0.0f;

        int awB = awH0 + buf * 576;
#pragma unroll
        for (int lv = 4; lv >= 1; lv--) {
            int i0 = (lv == 4) ? 0 : ((lv == 3) ? cum4 : ((lv == 2) ? cum3 : cum2));
            int i1 = (lv == 4) ? cum4 : ((lv == 3) ? cum3 : ((lv == 2) ? cum2 : cum1));
#pragma unroll 1
            for (int idx = i0; idx < i1; idx++) {
                int kc = (int)((ordv >> (4 * idx)) & 15ull);
                int ah = awB + kc * 8;
                int bh = blW + kc * 8;
                uint32_t w9[9];
#pragma unroll
                for (int u = 0; u < 9; u++) w9[u] = SW[ah + 4 * u];
                uint32_t bb[8];
#pragma unroll
                for (int gq = 0; gq < lv; gq++) {
                    bb[2 * gq]     = SW[bh + gq * 8 * BSTRIDE];
                    bb[2 * gq + 1] = SW[bh + gq * 8 * BSTRIDE + 4];
                }
#pragma unroll
                for (int gq = 0; gq < lv; gq++)
#pragma unroll
                    for (int ms = 0; ms < 4; ms++)
                        mma16816(d + (ms * 4 + gq) * 4,
                                 w9[2 * ms], w9[2 * ms + 1],
                                 w9[2 * ms + 1], w9[2 * ms + 2],
                                 bb[2 * gq], bb[2 * gq + 1]);
            }
        }

        // ---- epilogue: power -> smem stage -> coalesced STG.128 ----
        {
            int tb = mwarp + lq;
#pragma unroll
            for (int ms = 0; ms < 4; ms++) {
#pragma unroll
                for (int gq = 0; gq < 4; gq++) {
                    const float* dd = d + (ms * 4 + gq) * 4;
                    float p0 = dd[0] * dd[0] + dd[1] * dd[1];
                    float p1 = dd[2] * dd[2] + dd[3] * dd[3];
                    so[(tb + ms * 16) * 36 + lcol[gq]] = p0;
                    so[(tb + ms * 16 + 8) * 36 + lcol[gq]] = p1;
                }
            }
        }
        __syncthreads();   // barrier B: out stage complete
        {
            int rlane = lane >> 3, q = lane & 7;
            size_t obase = ((size_t)(b * LL + t0)) * (CC * RR) + c * RR + q * 4;
#pragma unroll
            for (int k = 0; k < 8; k++) {
                int row = wid * 32 + k * 4 + rlane;
                float4 v = *(const float4*)(so + row * 36 + q * 4);
                *(float4*)(out + obase + (size_t)row * (CC * RR)) = v;
            }
        }

        g = gn;
        buf ^= 1;
    }
}

extern "C" void kernel_launch(void* const* d_in, const int* in_sizes, int n_in,
                              void* d_out, int out_size) {
    const float* x  = (const float*)d_in[0];
    const float* kV = (const float*)d_in[1];
    const float* sV = (const float*)d_in[2];
    float* out = (float*)d_out;

    cudaFuncSetAttribute(conv_kernel, cudaFuncAttributeMaxDynamicSharedMemorySize,
                         SMEM_BYTES);

    // 1) Gabor bank (sigma-sorted, single fp16)
    bank_kernel<<<256, 256>>>(kV, sV);
    // 2) per-channel truncation tables + queue reset (parallel)
    table_kernel<<<CC, 32>>>(sV);
    // 3) persistent implicit-GEMM wavelet transform (coalesced epilogue)
    conv_kernel<<<NBLOCKS, NTHREADS, SMEM_BYTES>>>(x, out);
}

// round 17
// speedup vs baseline: 1.4917x; 1.0194x over previous
#include <cuda_runtime.h>
#include <cuda_fp16.h>
#include <math.h>
#include <stdint.h>

// Problem constants
#define BB 16
#define CC 8
#define LL 16384
#define RR 32

#define TM 256                 // t rows per CTA tile
#define NTILES 8192            // c-major: c=g>>10, b=(g>>6)&15, seg=g&63
#define NBLOCKS 304            // 2 CTAs per SM
#define NTHREADS 256           // 8 warps; warp = m64 x n-half (4 parity groups)

#define BSTRIDE 132            // uint32 words per B row (264 fp16, padded)

// SMEM layout (bytes)
#define BH_OFF 0                         // B: 64 rows * 132 words = 33792 B
#define PB_OFF 33792                     // window pair views, 2 buffers:
                                         //   buf*2304 + {PE:0, PO:1152}
#define SG_OFF (PB_OFF + 4608)           // queue slots [0],[1] + initial [2]
#define OUT_OFF (SG_OFF + 16)            // output stage: 256 rows * 36 floats
#define SMEM_BYTES (OUT_OFF + 256 * 36 * 4)   // ~75.3 KB -> 2 CTAs/SM

// Gabor bank, single fp16, padded: row n (0..63) = 2*pos + (0=re,1=im), tap w
__device__ __align__(16) __half g_bh[CC][64 * 2 * BSTRIDE];
__device__ int   g_pr[CC][32];      // sorted pos -> actual output r
// Per-half level tables, halves by GROUP PARITY (balanced work):
// [c][h]: groups {h, h+2, h+4, h+6}; .x/.y = kc order nibbles (count desc),
// .z = cum[1..4] bytes (cum[l] = #kc with >= l active groups in this half)
__device__ uint4 g_tab[CC][2];
__device__ unsigned int g_counter;

__global__ void bank_kernel(const float* __restrict__ kV, const float* __restrict__ sV) {
    int idx = blockIdx.x * blockDim.x + threadIdx.x;
    if (idx >= 65536) return;
    int f = idx >> 8, w = idx & 255;
    int c = f >> 5, j = f & 31;
    float k = kV[f], s = sV[f];

    // sort rank within channel, sigma DESC (pos 0 = largest sigma), tie by j
    int pos = 0;
    for (int j2 = 0; j2 < 32; j2++) {
        float s2 = sV[c * 32 + j2];
        pos += (s2 > s) || (s2 == s && j2 < j);
    }

    float phase = ((float)(-2.0 * M_PI / 256.0) * k) * (float)w;
    float sp, cp;
    sincosf(phase, &sp, &cp);     // ~1e-7 err, irrelevant vs fp16 floor
    float nm = (float)w - 128.0f;
    float s2v = s * s;
    float inv2s2 = 1.0f / (2.0f * s2v);
    float coef = 1.0f / sqrtf(2.0f * (float)M_PI * s2v);
    float gauss = coef * expf(-inv2s2 * nm * nm);

    g_bh[c][(2 * pos) * 264 + w] = __float2half(cp * gauss);
    g_bh[c][(2 * pos + 1) * 264 + w] = __float2half(sp * gauss);

    if (w == 0) g_pr[c][pos] = 31 - j;   // reference reverses R
}

// Parallel per-channel truncation tables (parity halves).
__global__ void table_kernel(const float* __restrict__ sV) {
    __shared__ float sg[32];
    __shared__ int kl[8], kh[8];
    int c = blockIdx.x;      // 0..7
    int j = threadIdx.x;     // 0..31
    float s = sV[c * 32 + j];
    int pos = 0;
    for (int j2 = 0; j2 < 32; j2++) {
        float s2 = sV[c * 32 + j2];
        pos += (s2 > s) || (s2 == s && j2 < j);
    }
    sg[pos] = s;             // sigma sorted descending
    __syncthreads();
    if (j < 8) {             // group gq support interval from its max sigma
        float D = 4.5f * sg[4 * j];
        int a = (int)floorf((128.0f - D) * (1.0f / 16.0f));
        int e = (int)floorf((128.0f + D) * (1.0f / 16.0f));
        kl[j] = a < 0 ? 0 : a;
        kh[j] = e > 15 ? 15 : e;
    }
    __syncthreads();
    if (j < 2) {             // per-parity-half counting sort of kc
        int cnt[16];
        for (int kc = 0; kc < 16; kc++) {
            int cn = 0;
            for (int q = 0; q < 4; q++) {
                int gq = 2 * q + j;   // parity-interleaved groups
                cn += (kl[gq] <= kc && kc <= kh[gq]);
            }
            cnt[kc] = cn;
        }
        unsigned long long ord = 0ull;
        int cum[6];
        int ip = 0;
        for (int l2 = 4; l2 >= 1; l2--) {
            for (int kc = 0; kc < 16; kc++)
                if (cnt[kc] == l2) {
                    ord |= (unsigned long long)kc << (4 * ip);
                    ip++;
                }
            cum[l2] = ip;
        }
        uint4 tab;
        tab.x = (unsigned int)(ord & 0xFFFFFFFFull);
        tab.y = (unsigned int)(ord >> 32);
        tab.z = (unsigned int)cum[1] | ((unsigned int)cum[2] << 8) |
                ((unsigned int)cum[3] << 16) | ((unsigned int)cum[4] << 24);
        tab.w = 0;
        g_tab[c][j] = tab;
    }
    if (c == 0 && j == 0) g_counter = 0;
}

__device__ __forceinline__ void mma16816(float* d,
                                         uint32_t a0, uint32_t a1, uint32_t a2, uint32_t a3,
                                         uint32_t b0, uint32_t b1) {
    asm volatile(
        "mma.sync.aligned.m16n8k16.row.col.f32.f16.f16.f32 "
        "{%0,%1,%2,%3}, {%4,%5,%6,%7}, {%8,%9}, {%0,%1,%2,%3};"
        : "+f"(d[0]), "+f"(d[1]), "+f"(d[2]), "+f"(d[3])
        : "r"(a0), "r"(a1), "r"(a2), "r"(a3), "r"(b0), "r"(b1));
}

__global__ void __launch_bounds__(NTHREADS, 2)
conv_kernel(const float* __restrict__ x, float* __restrict__ out) {
    extern __shared__ unsigned char smem[];
    const uint32_t* SW = (const uint32_t*)smem;     // word-indexed smem base
    unsigned int* sgp = (unsigned int*)(smem + SG_OFF);
    float* so = (float*)(smem + OUT_OFF);           // output stage [256][36]

    int tid  = threadIdx.x;
    int wid  = tid >> 5;
    int lane = tid & 31;
    int lq   = lane >> 2;     // 0..7
    int lr   = lane & 3;      // 0..3
    int half = wid & 1;       // parity half: groups {half, half+2, half+4, half+6}
    int mwarp = (wid >> 1) * 64;
    int odd = lq & 1;
    int abase = (mwarp >> 1) + (lq >> 1) + lr;

    // word offsets: A pair view base (without buffer), B rows in staged SMEM.
    // local group q (0..3) -> global group 2q+half -> B rows at
    // (2q+half)*8*BSTRIDE = half*8*BSTRIDE + q*16*BSTRIDE
    int awH0 = (PB_OFF + (odd ? 1152 : 0)) / 4 + abase;
    int blW  = BH_OFF / 4 + half * 8 * BSTRIDE + lq * BSTRIDE + lr;

    if (tid == 0) sgp[2] = atomicAdd(&g_counter, 1u);
    __syncthreads();
    unsigned int g = sgp[2];

    // prefetch first tile's x window: window[j] = x[b, t0-128+j, c], j<544
    float v0 = 0, v1 = 0;
    {
        unsigned int gc = (g < NTILES) ? g : 0u;
        int c2 = gc >> 10, b2 = (gc >> 6) & 15, t02 = (int)(gc & 63) << 8;
        const float* xb = x + (size_t)b2 * LL * CC + c2;
        int l = t02 - 128 + tid;
        v0 = (l >= 0 && l < LL) ? xb[(size_t)l * CC] : 0.0f;
        if (tid < 288) {
            int l1 = l + 256;
            v1 = (l1 >= 0 && l1 < LL) ? xb[(size_t)l1 * CC] : 0.0f;
        }
    }

    int cur_c = -1;
    unsigned long long ordv = 0ull;
    int cum1 = 0, cum2 = 0, cum3 = 0, cum4 = 0;
    int lcol[4];
    int buf = 0;
    while (g < NTILES) {
        int c = g >> 10, b = (g >> 6) & 15, t0 = (int)(g & 63) << 8;

        // store fp16 window into THIS buffer (alternating buffers)
        {
            __half* PEh = (__half*)(smem + PB_OFF + buf * 2304);
            __half* POh = PEh + 576;     // 1152 B later
            __half h0 = __float2half(v0);
            PEh[tid] = h0;
            if (tid > 0) POh[tid - 1] = h0;
            if (tid < 288) {
                __half h1 = __float2half(v1);
                PEh[256 + tid] = h1;
                POh[255 + tid] = h1;
            }
        }

        if (c != cur_c) {  // stage B for this channel (rare; own barrier)
            __syncthreads();           // protect previous tile's B readers
            const uint4* sH = (const uint4*)g_bh[c];
            uint4* dH = (uint4*)(smem + BH_OFF);
            for (int i = tid; i < 2112; i += NTHREADS) dH[i] = sH[i];
            uint4 tab = g_tab[c][half];
            ordv = (unsigned long long)tab.x | ((unsigned long long)tab.y << 32);
            cum1 = (int)(tab.z & 255u);
            cum2 = (int)((tab.z >> 8) & 255u);
            cum3 = (int)((tab.z >> 16) & 255u);
            cum4 = (int)((tab.z >> 24) & 255u);
#pragma unroll
            for (int q = 0; q < 4; q++)
                lcol[q] = g_pr[c][(2 * q + half) * 4 + lr];
            cur_c = c;
        }

        if (tid == 0) sgp[buf] = atomicAdd(&g_counter, 1u);
        __syncthreads();   // barrier A: window+B+id visible; prev out reads done
        unsigned int gn = sgp[buf];

        // prefetch next tile's x (hidden under the MMA mainloop)
        {
            unsigned int gc = (gn < NTILES) ? gn : 0u;
            int c2 = gc >> 10, b2 = (gc >> 6) & 15, t02 = (int)(gc & 63) << 8;
            const float* xb = x + (size_t)b2 * LL * CC + c2;
            int l = t02 - 128 + tid;
            v0 = (l >= 0 && l < LL) ? xb[(size_t)l * CC] : 0.0f;
            if (tid < 288) {
                int l1 = l + 256;
                v1 = (l1 >= 0 && l1 < LL) ? xb[(size_t)l1 * CC] : 0.0f;
            }
        }

        // ---- single-pass fp16 GEMM, parity-half level-loop truncation ----
        float d[64];
#pragma unroll
        for (int i = 0; i < 64; i++) d[i] = 0.0f;

        int awB = awH0 + buf * 576;
#pragma unroll
        for (int lv = 4; lv >= 1; lv--) {
            int i0 = (lv == 4) ? 0 : ((lv == 3) ? cum4 : ((lv == 2) ? cum3 : cum2));
            int i1 = (lv == 4) ? cum4 : ((lv == 3) ? cum3 : ((lv == 2) ? cum2 : cum1));
#pragma unroll 1
            for (int idx = i0; idx < i1; idx++) {
                int kc = (int)((ordv >> (4 * idx)) & 15ull);
                int ah = awB + kc * 8;
                int bh = blW + kc * 8;
                uint32_t w9[9];
#pragma unroll
                for (int u = 0; u < 9; u++) w9[u] = SW[ah + 4 * u];
                uint32_t bb[8];
#pragma unroll
                for (int q = 0; q < lv; q++) {
                    bb[2 * q]     = SW[bh + q * 16 * BSTRIDE];
                    bb[2 * q + 1] = SW[bh + q * 16 * BSTRIDE + 4];
                }
#pragma unroll
                for (int q = 0; q < lv; q++)
#pragma unroll
                    for (int ms = 0; ms < 4; ms++)
                        mma16816(d + (ms * 4 + q) * 4,
                                 w9[2 * ms], w9[2 * ms + 1],
                                 w9[2 * ms + 1], w9[2 * ms + 2],
                                 bb[2 * q], bb[2 * q + 1]);
            }
        }

        // ---- epilogue: power -> smem stage -> coalesced STG.128 ----
        {
            int tb = mwarp + lq;
#pragma unroll
            for (int ms = 0; ms < 4; ms++) {
#pragma unroll
                for (int q = 0; q < 4; q++) {
                    const float* dd = d + (ms * 4 + q) * 4;
                    float p0 = dd[0] * dd[0] + dd[1] * dd[1];
                    float p1 = dd[2] * dd[2] + dd[3] * dd[3];
                    so[(tb + ms * 16) * 36 + lcol[q]] = p0;
                    so[(tb + ms * 16 + 8) * 36 + lcol[q]] = p1;
                }
            }
        }
        __syncthreads();   // barrier B: out stage complete
        {
            int rlane = lane >> 3, q = lane & 7;
            size_t obase = ((size_t)(b * LL + t0)) * (CC * RR) + c * RR + q * 4;
#pragma unroll
            for (int k = 0; k < 8; k++) {
                int row = wid * 32 + k * 4 + rlane;
                float4 v = *(const float4*)(so + row * 36 + q * 4);
                *(float4*)(out + obase + (size_t)row * (CC * RR)) = v;
            }
        }

        g = gn;
        buf ^= 1;
    }
}

extern "C" void kernel_launch(void* const* d_in, const int* in_sizes, int n_in,
                              void* d_out, int out_size) {
    const float* x  = (const float*)d_in[0];
    const float* kV = (const float*)d_in[1];
    const float* sV = (const float*)d_in[2];
    float* out = (float*)d_out;

    cudaFuncSetAttribute(conv_kernel, cudaFuncAttributeMaxDynamicSharedMemorySize,
                         SMEM_BYTES);

    // 1) Gabor bank (sigma-sorted, single fp16, sincosf)
    bank_kernel<<<256, 256>>>(kV, sV);
    // 2) per-channel parity-half truncation tables + queue reset
    table_kernel<<<CC, 32>>>(sV);
    // 3) persistent implicit-GEMM wavelet transform (balanced halves)
    conv_kernel<<<NBLOCKS, NTHREADS, SMEM_BYTES>>>(x, out);
}